// round 7
// baseline (speedup 1.0000x reference)
#include <cuda_runtime.h>
#include <cuda_fp16.h>
#include <cstdint>
#include <cstddef>

// ---------------- problem constants ----------------
#define B_   8
#define T_   12
#define P_   1000
#define N_   20000
#define E_   60000
#define FP_  32
#define FN_  32
#define H_   12
#define KD_  384                 // GEMM1 K (nodes_x half only)
#define HID_ 768
#define M_   (B_ * N_)           // 160000 rows
#define BP_  (B_ * P_)           // 8000 distinct patch rows

// ---------------- device scratch (static; no allocs allowed) ----------------
__device__ __half g_X[(size_t)M_ * KD_];    // fp16 nodes_x features, [b*N+n][384]
__device__ __half g_W1t[HID_ * KD_];        // W1 top half transposed:  [h][k], k<384
__device__ __half g_W1bt[HID_ * KD_];       // W1 bottom half transposed
__device__ __half g_Pf[BP_ * KD_];          // patch rows fp16
__device__ __half g_PW[(size_t)BP_ * HID_]; // PW = Pf @ W1_bot
__device__ int    g_off[N_ + 1];
__device__ int    g_edgep[E_];

// ---------------- fused conversions ----------------
#define W1T_WORK (HID_ * HID_)
#define NX_WORK  (B_ * T_ * N_ * 4)
#define PF_WORK  (B_ * T_ * P_ * 4)
__global__ void k_conv(const float* __restrict__ W1, const float* __restrict__ nodes_x,
                       const float* __restrict__ patch) {
    int i = blockIdx.x * blockDim.x + threadIdx.x;
    if (i < W1T_WORK) {
        int k = i / HID_, h = i % HID_;
        __half v = __float2half_rn(W1[i]);
        if (k < KD_) g_W1t[h * KD_ + k] = v;
        else         g_W1bt[h * KD_ + (k - KD_)] = v;
    } else if (i < W1T_WORK + NX_WORK) {
        int j = i - W1T_WORK;
        int q  = j & 3;
        int n  = (j >> 2) % N_;
        int bt = (j >> 2) / N_;
        int b = bt / T_, t = bt % T_;
        const float4* src = (const float4*)(nodes_x + ((size_t)bt * N_ + n) * FN_ + q * 8);
        float4 a = src[0], c = src[1];
        union { __half2 h[4]; uint4 u; } cv;
        cv.h[0] = __floats2half2_rn(a.x, a.y);
        cv.h[1] = __floats2half2_rn(a.z, a.w);
        cv.h[2] = __floats2half2_rn(c.x, c.y);
        cv.h[3] = __floats2half2_rn(c.z, c.w);
        *(uint4*)&g_X[((size_t)(b * N_ + n)) * KD_ + t * FN_ + q * 8] = cv.u;
    } else if (i < W1T_WORK + NX_WORK + PF_WORK) {
        int j = i - W1T_WORK - NX_WORK;
        int q  = j & 3;
        int p  = (j >> 2) % P_;
        int bt = (j >> 2) / P_;
        int b = bt / T_, t = bt % T_;
        const float4* src = (const float4*)(patch + ((size_t)bt * P_ + p) * FP_ + q * 8);
        float4 a = src[0], c = src[1];
        union { __half2 h[4]; uint4 u; } cv;
        cv.h[0] = __floats2half2_rn(a.x, a.y);
        cv.h[1] = __floats2half2_rn(a.z, a.w);
        cv.h[2] = __floats2half2_rn(c.x, c.y);
        cv.h[3] = __floats2half2_rn(c.z, c.w);
        *(uint4*)&g_Pf[((size_t)(b * P_ + p)) * KD_ + t * FP_ + q * 8] = cv.u;
    }
}

// ---------------- single-block CSR build ----------------
__global__ void k_csr(const int* __restrict__ mapper, const int* __restrict__ batch) {
    extern __shared__ int scnt[];
    __shared__ int buf[1024];
    __shared__ int carry;
    int t = threadIdx.x;
    for (int i = t; i < N_; i += 1024) scnt[i] = 0;
    __syncthreads();
    for (int e = t; e < E_; e += 1024) atomicAdd(&scnt[mapper[e]], 1);
    __syncthreads();
    if (t == 0) { carry = 0; g_off[0] = 0; }
    __syncthreads();
    for (int base = 0; base < N_; base += 1024) {
        int i = base + t;
        int v = (i < N_) ? scnt[i] : 0;
        buf[t] = v;
        __syncthreads();
        for (int s = 1; s < 1024; s <<= 1) {
            int add = (t >= s) ? buf[t - s] : 0;
            __syncthreads();
            buf[t] += add;
            __syncthreads();
        }
        int incl = buf[t] + carry;
        if (i < N_) { g_off[i + 1] = incl; scnt[i] = incl - v; }
        __syncthreads();
        if (t == 1023) carry = incl;
        __syncthreads();
    }
    for (int e = t; e < E_; e += 1024) {
        int n = mapper[e];
        int idx = atomicAdd(&scnt[n], 1);
        g_edgep[idx] = batch[e];
    }
}

// ---------------- mma helpers ----------------
__device__ __forceinline__ uint32_t smem_u32(const void* p) {
    uint32_t a;
    asm volatile("{ .reg .u64 t; cvta.to.shared.u64 t, %1; cvt.u32.u64 %0, t; }"
                 : "=r"(a) : "l"(p));
    return a;
}
__device__ __forceinline__ void ldsm4(uint32_t* r, uint32_t addr) {
    asm volatile("ldmatrix.sync.aligned.m8n8.x4.shared.b16 {%0,%1,%2,%3}, [%4];"
                 : "=r"(r[0]), "=r"(r[1]), "=r"(r[2]), "=r"(r[3]) : "r"(addr));
}
__device__ __forceinline__ void mma16816(float* c, const uint32_t* a,
                                         uint32_t b0, uint32_t b1) {
    asm volatile("mma.sync.aligned.m16n8k16.row.col.f32.f16.f16.f32 "
                 "{%0,%1,%2,%3}, {%4,%5,%6,%7}, {%8,%9}, {%0,%1,%2,%3};"
                 : "+f"(c[0]), "+f"(c[1]), "+f"(c[2]), "+f"(c[3])
                 : "r"(a[0]), "r"(a[1]), "r"(a[2]), "r"(a[3]), "r"(b0), "r"(b1));
}
#define CPASYNC16(dst, src) \
    asm volatile("cp.async.cg.shared.global [%0], [%1], 16;" :: "r"(dst), "l"(src))
#define CPCOMMIT() asm volatile("cp.async.commit_group;" ::: "memory")
#define CPWAIT1()  asm volatile("cp.async.wait_group 1;" ::: "memory")
#define CPWAIT0()  asm volatile("cp.async.wait_group 0;" ::: "memory")

// ---------------- k_pw: PW[8000,768] = Pf @ W1bt^T (unchanged, works) ----------------
#define PW_PITCH 80
#define PW_STAGE (192 * PW_PITCH)
__global__ void __launch_bounds__(256, 1)
k_pw()
{
    __shared__ char smem[3 * PW_STAGE];
    const int tid   = threadIdx.x;
    const int lane  = tid & 31;
    const int wid   = tid >> 5;
    const int warpM = wid >> 2;
    const int warpN = wid & 3;
    const int m0    = blockIdx.x * 64;
    const int n0    = blockIdx.y * 128;
    const uint32_t tile_base = smem_u32(smem);
    const int r0 = tid >> 2;
    const int c0 = tid & 3;

    float acc[2][4][4];
#pragma unroll
    for (int mf = 0; mf < 2; ++mf)
#pragma unroll
        for (int nf = 0; nf < 4; ++nf)
#pragma unroll
            for (int q = 0; q < 4; ++q) acc[mf][nf][q] = 0.0f;

#pragma unroll
    for (int s = 0; s < 2; ++s) {
        const int k0 = s * 32;
        uint32_t sA = tile_base + s * PW_STAGE;
        uint32_t sB = sA + 64 * PW_PITCH;
        CPASYNC16(sA + r0 * PW_PITCH + c0 * 16,
                  (const void*)&g_Pf[(size_t)(m0 + r0) * KD_ + k0 + c0 * 8]);
        CPASYNC16(sB + r0 * PW_PITCH + c0 * 16,
                  (const void*)&g_W1bt[(size_t)(n0 + r0) * KD_ + k0 + c0 * 8]);
        CPASYNC16(sB + (r0 + 64) * PW_PITCH + c0 * 16,
                  (const void*)&g_W1bt[(size_t)(n0 + r0 + 64) * KD_ + k0 + c0 * 8]);
        CPCOMMIT();
    }

#pragma unroll 1
    for (int kt = 0; kt < 12; ++kt) {
        if (kt < 11) { CPWAIT1(); } else { CPWAIT0(); }
        __syncthreads();
        if (kt + 2 < 12) {
            const int k0 = (kt + 2) * 32;
            const int st = (kt + 2) % 3;
            uint32_t sA = tile_base + st * PW_STAGE;
            uint32_t sB = sA + 64 * PW_PITCH;
            CPASYNC16(sA + r0 * PW_PITCH + c0 * 16,
                      (const void*)&g_Pf[(size_t)(m0 + r0) * KD_ + k0 + c0 * 8]);
            CPASYNC16(sB + r0 * PW_PITCH + c0 * 16,
                      (const void*)&g_W1bt[(size_t)(n0 + r0) * KD_ + k0 + c0 * 8]);
            CPASYNC16(sB + (r0 + 64) * PW_PITCH + c0 * 16,
                      (const void*)&g_W1bt[(size_t)(n0 + r0 + 64) * KD_ + k0 + c0 * 8]);
            CPCOMMIT();
        }
        const int st = kt % 3;
        uint32_t sA = tile_base + st * PW_STAGE;
        uint32_t sB = sA + 64 * PW_PITCH;
#pragma unroll
        for (int ks = 0; ks < 2; ++ks) {
            uint32_t afr[2][4], bfr[2][4];
#pragma unroll
            for (int mf = 0; mf < 2; ++mf) {
                uint32_t addr = sA + (warpM * 32 + mf * 16 + (lane & 15)) * PW_PITCH
                                   + (ks * 2 + (lane >> 4)) * 16;
                ldsm4(afr[mf], addr);
            }
#pragma unroll
            for (int nq = 0; nq < 2; ++nq) {
                uint32_t addr = sB + (warpN * 32 + nq * 16 + (lane & 7) + ((lane >> 4) & 1) * 8) * PW_PITCH
                                   + (ks * 2 + ((lane >> 3) & 1)) * 16;
                ldsm4(bfr[nq], addr);
            }
#pragma unroll
            for (int mf = 0; mf < 2; ++mf)
#pragma unroll
                for (int nq = 0; nq < 2; ++nq) {
                    mma16816(acc[mf][nq * 2],     afr[mf], bfr[nq][0], bfr[nq][1]);
                    mma16816(acc[mf][nq * 2 + 1], afr[mf], bfr[nq][2], bfr[nq][3]);
                }
        }
    }
#pragma unroll
    for (int mf = 0; mf < 2; ++mf)
#pragma unroll
        for (int hr = 0; hr < 2; ++hr) {
            int row = m0 + warpM * 32 + mf * 16 + hr * 8 + (lane >> 2);
#pragma unroll
            for (int nf = 0; nf < 4; ++nf) {
                int col = n0 + warpN * 32 + nf * 8 + (lane & 3) * 2;
                __half2 h = __floats2half2_rn(acc[mf][nf][2 * hr], acc[mf][nf][2 * hr + 1]);
                *(__half2*)&g_PW[(size_t)row * HID_ + col] = h;
            }
        }
}

// ---------------- main GEMM: CTA tile 128x256, K-chunk 64, 8 warps (warp 32x128) ----------
// smem (bytes): W2 @0 (36864) | b1 @36864 (3072) | mean @39936 (65536 fp16)
//               tiles @105472: 2 stages * (128+256)*144 = 110592  => total 216064
#define SM_W2    0
#define SM_B1    36864
#define SM_MEAN  39936
#define SM_TILE  105472
#define RP_      144
#define STAGE_BYTES ((128 + 256) * RP_)   // 55296
#define SMEM_BYTES  216064

#define NT_   3
#define KT_   6                 // 384 / 64
#define KTG_  (NT_ * KT_)       // 18

__global__ void __launch_bounds__(256, 1)
k_gemm(const float* __restrict__ b1, const float* __restrict__ W2,
       const float* __restrict__ b2, float* __restrict__ out)
{
    extern __shared__ char smem[];
    const int tid   = threadIdx.x;
    const int lane  = tid & 31;
    const int wid   = tid >> 5;
    const int warpM = wid >> 1;          // 0..3
    const int warpN = wid & 1;           // 0..1
    const int m0    = blockIdx.x * 128;

    float*  w2s  = (float*)(smem + SM_W2);
    float*  b1s  = (float*)(smem + SM_B1);
    __half* mns  = (__half*)(smem + SM_MEAN);   // [128][256]
    const uint32_t tile_base = smem_u32(smem + SM_TILE);

    for (int i = tid; i < HID_ * H_; i += 256) w2s[i] = W2[i];
    for (int i = tid; i < HID_;      i += 256) b1s[i] = b1[i];
    __syncthreads();

    float pers[4][3];
#pragma unroll
    for (int i = 0; i < 4; ++i)
#pragma unroll
        for (int j = 0; j < 3; ++j) pers[i][j] = 0.0f;

    float acc[2][16][4];
#pragma unroll
    for (int mf = 0; mf < 2; ++mf)
#pragma unroll
        for (int nf = 0; nf < 16; ++nf)
#pragma unroll
            for (int q = 0; q < 4; ++q) acc[mf][nf][q] = 0.0f;

    // ---- preload stage 0 (ktg=0: n0=0, k0=0) ----
    {
        uint32_t sA = tile_base;
        uint32_t sB = sA + 128 * RP_;
#pragma unroll
        for (int i = 0; i < 4; ++i) {
            int idx = tid + i * 256;
            int r = idx >> 3, c = idx & 7;
            CPASYNC16(sA + r * RP_ + c * 16,
                      (const void*)&g_X[(size_t)(m0 + r) * KD_ + c * 8]);
        }
#pragma unroll
        for (int i = 0; i < 8; ++i) {
            int idx = tid + i * 256;
            int r = idx >> 3, c = idx & 7;
            CPASYNC16(sB + r * RP_ + c * 16,
                      (const void*)&g_W1t[(size_t)r * KD_ + c * 8]);
        }
        CPCOMMIT();
    }

#pragma unroll 1
    for (int ktg = 0; ktg < KTG_; ++ktg) {
        CPWAIT0();
        __syncthreads();

        // prefetch next stage (overlaps with compute below)
        if (ktg + 1 < KTG_) {
            const int pg  = ktg + 1;
            const int pk0 = (pg % KT_) * 64;
            const int pn0 = (pg / KT_) * 256;
            uint32_t sA = tile_base + (pg & 1) * STAGE_BYTES;
            uint32_t sB = sA + 128 * RP_;
#pragma unroll
            for (int i = 0; i < 4; ++i) {
                int idx = tid + i * 256;
                int r = idx >> 3, c = idx & 7;
                CPASYNC16(sA + r * RP_ + c * 16,
                          (const void*)&g_X[(size_t)(m0 + r) * KD_ + pk0 + c * 8]);
            }
#pragma unroll
            for (int i = 0; i < 8; ++i) {
                int idx = tid + i * 256;
                int r = idx >> 3, c = idx & 7;
                CPASYNC16(sB + r * RP_ + c * 16,
                          (const void*)&g_W1t[(size_t)(pn0 + r) * KD_ + pk0 + c * 8]);
            }
            CPCOMMIT();
        }

        // ---- compute current stage: 4 k16 chunks x 8 n16 blocks ----
        {
            uint32_t sA = tile_base + (ktg & 1) * STAGE_BYTES;
            uint32_t sB = sA + 128 * RP_;
#pragma unroll
            for (int ks = 0; ks < 4; ++ks) {
                uint32_t afr[2][4];
#pragma unroll
                for (int mf = 0; mf < 2; ++mf) {
                    uint32_t addr = sA + (warpM * 32 + mf * 16 + (lane & 15)) * RP_
                                       + ks * 32 + (lane >> 4) * 16;
                    ldsm4(afr[mf], addr);
                }
#pragma unroll
                for (int nq = 0; nq < 8; ++nq) {
                    uint32_t bfr[4];
                    uint32_t addr = sB + (warpN * 128 + nq * 16 + (lane & 7) + ((lane >> 4) & 1) * 8) * RP_
                                       + ks * 32 + ((lane >> 3) & 1) * 16;
                    ldsm4(bfr, addr);
#pragma unroll
                    for (int mf = 0; mf < 2; ++mf) {
                        mma16816(acc[mf][nq * 2],     afr[mf], bfr[0], bfr[1]);
                        mma16816(acc[mf][nq * 2 + 1], afr[mf], bfr[2], bfr[3]);
                    }
                }
            }
        }

        // ---- n-tile boundary: cooperative coalesced mean gather + epilogue ----
        if ((ktg % KT_) == (KT_ - 1)) {
            const int n0 = (ktg / KT_) * 256;

            // gather: each warp handles 16 rows; lane covers 8 contiguous cols (16B)
#pragma unroll 1
            for (int j = 0; j < 16; ++j) {
                int r  = wid * 16 + j;
                int m  = m0 + r;
                int bb = m / N_;
                int nn = m - bb * N_;
                int eb = g_off[nn];
                int ec = g_off[nn + 1] - eb;
                float inv = 1.0f / fmaxf((float)ec, 1.0f);
                float fs[8];
#pragma unroll
                for (int o = 0; o < 8; ++o) fs[o] = 0.0f;
                for (int e = 0; e < ec; ++e) {
                    int pp = g_edgep[eb + e];
                    uint4 v = *(const uint4*)&g_PW[((size_t)(bb * P_ + pp)) * HID_ + n0 + lane * 8];
                    union { uint4 u; __half2 h[4]; } cv; cv.u = v;
#pragma unroll
                    for (int o = 0; o < 4; ++o) {
                        float2 f = __half22float2(cv.h[o]);
                        fs[o * 2]     += f.x;
                        fs[o * 2 + 1] += f.y;
                    }
                }
                union { uint4 u; __half2 h[4]; } ov;
#pragma unroll
                for (int o = 0; o < 4; ++o)
                    ov.h[o] = __floats2half2_rn(fs[o * 2] * inv, fs[o * 2 + 1] * inv);
                *(uint4*)&mns[r * 256 + lane * 8] = ov.u;
            }
            __syncthreads();

            // epilogue: acc + mean + b1, relu, fold GEMM2 into pers
#pragma unroll
            for (int mf = 0; mf < 2; ++mf) {
#pragma unroll
                for (int hr = 0; hr < 2; ++hr) {
                    const int rowL = warpM * 32 + mf * 16 + hr * 8 + (lane >> 2);
                    float p[12];
#pragma unroll
                    for (int o = 0; o < 12; ++o) p[o] = 0.0f;
#pragma unroll
                    for (int nf = 0; nf < 16; ++nf) {
                        int cl  = warpN * 128 + nf * 8 + (lane & 3) * 2;
                        int col0 = n0 + cl;
                        float2 mf2 = __half22float2(*(const __half2*)&mns[rowL * 256 + cl]);
                        float v0 = fmaxf(acc[mf][nf][2 * hr]     + mf2.x + b1s[col0],     0.0f);
                        float v1 = fmaxf(acc[mf][nf][2 * hr + 1] + mf2.y + b1s[col0 + 1], 0.0f);
                        const float4* wp0 = (const float4*)(w2s + col0 * 12);
                        const float4* wp1 = (const float4*)(w2s + (col0 + 1) * 12);
                        float4 a0 = wp0[0], a1 = wp0[1], a2 = wp0[2];
                        float4 d0 = wp1[0], d1 = wp1[1], d2 = wp1[2];
                        p[0]  += v0 * a0.x + v1 * d0.x;  p[1]  += v0 * a0.y + v1 * d0.y;
                        p[2]  += v0 * a0.z + v1 * d0.z;  p[3]  += v0 * a0.w + v1 * d0.w;
                        p[4]  += v0 * a1.x + v1 * d1.x;  p[5]  += v0 * a1.y + v1 * d1.y;
                        p[6]  += v0 * a1.z + v1 * d1.z;  p[7]  += v0 * a1.w + v1 * d1.w;
                        p[8]  += v0 * a2.x + v1 * d2.x;  p[9]  += v0 * a2.y + v1 * d2.y;
                        p[10] += v0 * a2.z + v1 * d2.z;  p[11] += v0 * a2.w + v1 * d2.w;
                    }
#pragma unroll
                    for (int o = 0; o < 12; ++o) {
                        p[o] += __shfl_xor_sync(0xffffffffu, p[o], 1);
                        p[o] += __shfl_xor_sync(0xffffffffu, p[o], 2);
                    }
                    int q = lane & 3;
                    pers[mf * 2 + hr][0] += p[3 * q + 0];
                    pers[mf * 2 + hr][1] += p[3 * q + 1];
                    pers[mf * 2 + hr][2] += p[3 * q + 2];
                }
            }
#pragma unroll
            for (int mf = 0; mf < 2; ++mf)
#pragma unroll
                for (int nf = 0; nf < 16; ++nf)
#pragma unroll
                    for (int q = 0; q < 4; ++q) acc[mf][nf][q] = 0.0f;
            __syncthreads();   // mean buffer safe to reuse next n-tile
        }
    }

    // ---- cross-warpN reduce (reuse mean region), then global write ----
    float* red = (float*)(smem + SM_MEAN);  // 128*12 floats
    __syncthreads();
    if (warpN == 1) {
#pragma unroll
        for (int i = 0; i < 4; ++i) {
            int mf = i >> 1, hr = i & 1;
            int rowL = warpM * 32 + mf * 16 + hr * 8 + (lane >> 2);
            int q = lane & 3;
#pragma unroll
            for (int j = 0; j < 3; ++j)
                red[rowL * 12 + 3 * q + j] = pers[i][j];
        }
    }
    __syncthreads();
    if (warpN == 0) {
#pragma unroll
        for (int i = 0; i < 4; ++i) {
            int mf = i >> 1, hr = i & 1;
            int rowL = warpM * 32 + mf * 16 + hr * 8 + (lane >> 2);
            int q = lane & 3;
            size_t row = (size_t)(m0 + rowL);
#pragma unroll
            for (int j = 0; j < 3; ++j) {
                int o = 3 * q + j;
                out[row * 12 + o] = pers[i][j] + red[rowL * 12 + o] + b2[o];
            }
        }
    }
}

// ---------------- launch ----------------
extern "C" void kernel_launch(void* const* d_in, const int* in_sizes, int n_in,
                              void* d_out, int out_size)
{
    const float* patch  = (const float*)d_in[0];
    const float* nodes  = (const float*)d_in[1];
    const int*   batch  = (const int*)d_in[2];
    const int*   mapper = (const int*)d_in[3];
    const float* W1     = (const float*)d_in[4];
    const float* b1     = (const float*)d_in[5];
    const float* W2     = (const float*)d_in[6];
    const float* b2     = (const float*)d_in[7];
    float*       out    = (float*)d_out;

    k_conv<<<(W1T_WORK + NX_WORK + PF_WORK + 255) / 256, 256>>>(W1, nodes, patch);  // 0
    dim3 pwgrid(BP_ / 64, HID_ / 128);
    k_pw<<<pwgrid, 256>>>();                                                        // 1
    cudaFuncSetAttribute(k_csr, cudaFuncAttributeMaxDynamicSharedMemorySize, N_ * 4);
    k_csr<<<1, 1024, N_ * 4>>>(mapper, batch);                                      // 2
    cudaFuncSetAttribute(k_gemm, cudaFuncAttributeMaxDynamicSharedMemorySize, SMEM_BYTES);
    k_gemm<<<M_ / 128, 256, SMEM_BYTES>>>(b1, W2, b2, out);                         // 3
}

// round 8
// speedup vs baseline: 1.3862x; 1.3862x over previous
#include <cuda_runtime.h>
#include <cuda_fp16.h>
#include <cstdint>
#include <cstddef>

// ---------------- problem constants ----------------
#define B_   8
#define T_   12
#define P_   1000
#define N_   20000
#define E_   60000
#define FP_  32
#define FN_  32
#define H_   12
#define KD_  384                 // GEMM1 K after PW split
#define HID_ 768
#define M_   (B_ * N_)           // 160000 rows
#define BP_  (B_ * P_)           // 8000 distinct patch rows

// ---------------- device scratch ----------------
__device__ __half g_X[(size_t)M_ * KD_];
__device__ __half g_W1t[HID_ * KD_];        // W1 top half transposed
__device__ __half g_W1bt[HID_ * KD_];       // W1 bottom half transposed
__device__ __half g_Pf[BP_ * KD_];
__device__ __half g_PW[(size_t)BP_ * HID_];
__device__ int    g_off[N_ + 1];
__device__ int    g_edgep[E_];

// ---------------- fused conversions ----------------
#define W1T_WORK (HID_ * HID_)
#define NX_WORK  (B_ * T_ * N_ * 4)
#define PF_WORK  (B_ * T_ * P_ * 4)
__global__ void k_conv(const float* __restrict__ W1, const float* __restrict__ nodes_x,
                       const float* __restrict__ patch) {
    int i = blockIdx.x * blockDim.x + threadIdx.x;
    if (i < W1T_WORK) {
        int k = i / HID_, h = i % HID_;
        __half v = __float2half_rn(W1[i]);
        if (k < KD_) g_W1t[h * KD_ + k] = v;
        else         g_W1bt[h * KD_ + (k - KD_)] = v;
    } else if (i < W1T_WORK + NX_WORK) {
        int j = i - W1T_WORK;
        int q  = j & 3;
        int n  = (j >> 2) % N_;
        int bt = (j >> 2) / N_;
        int b = bt / T_, t = bt % T_;
        const float4* src = (const float4*)(nodes_x + ((size_t)bt * N_ + n) * FN_ + q * 8);
        float4 a = src[0], c = src[1];
        union { __half2 h[4]; uint4 u; } cv;
        cv.h[0] = __floats2half2_rn(a.x, a.y);
        cv.h[1] = __floats2half2_rn(a.z, a.w);
        cv.h[2] = __floats2half2_rn(c.x, c.y);
        cv.h[3] = __floats2half2_rn(c.z, c.w);
        *(uint4*)&g_X[((size_t)(b * N_ + n)) * KD_ + t * FN_ + q * 8] = cv.u;
    } else if (i < W1T_WORK + NX_WORK + PF_WORK) {
        int j = i - W1T_WORK - NX_WORK;
        int q  = j & 3;
        int p  = (j >> 2) % P_;
        int bt = (j >> 2) / P_;
        int b = bt / T_, t = bt % T_;
        const float4* src = (const float4*)(patch + ((size_t)bt * P_ + p) * FP_ + q * 8);
        float4 a = src[0], c = src[1];
        union { __half2 h[4]; uint4 u; } cv;
        cv.h[0] = __floats2half2_rn(a.x, a.y);
        cv.h[1] = __floats2half2_rn(a.z, a.w);
        cv.h[2] = __floats2half2_rn(c.x, c.y);
        cv.h[3] = __floats2half2_rn(c.z, c.w);
        *(uint4*)&g_Pf[((size_t)(b * P_ + p)) * KD_ + t * FP_ + q * 8] = cv.u;
    }
}

// ---------------- single-block CSR build ----------------
__global__ void k_csr(const int* __restrict__ mapper, const int* __restrict__ batch) {
    extern __shared__ int scnt[];
    __shared__ int buf[1024];
    __shared__ int carry;
    int t = threadIdx.x;
    for (int i = t; i < N_; i += 1024) scnt[i] = 0;
    __syncthreads();
    for (int e = t; e < E_; e += 1024) atomicAdd(&scnt[mapper[e]], 1);
    __syncthreads();
    if (t == 0) { carry = 0; g_off[0] = 0; }
    __syncthreads();
    for (int base = 0; base < N_; base += 1024) {
        int i = base + t;
        int v = (i < N_) ? scnt[i] : 0;
        buf[t] = v;
        __syncthreads();
        for (int s = 1; s < 1024; s <<= 1) {
            int add = (t >= s) ? buf[t - s] : 0;
            __syncthreads();
            buf[t] += add;
            __syncthreads();
        }
        int incl = buf[t] + carry;
        if (i < N_) { g_off[i + 1] = incl; scnt[i] = incl - v; }
        __syncthreads();
        if (t == 1023) carry = incl;
        __syncthreads();
    }
    for (int e = t; e < E_; e += 1024) {
        int n = mapper[e];
        int idx = atomicAdd(&scnt[n], 1);
        g_edgep[idx] = batch[e];
    }
}

// ---------------- mma helpers ----------------
__device__ __forceinline__ uint32_t smem_u32(const void* p) {
    uint32_t a;
    asm volatile("{ .reg .u64 t; cvta.to.shared.u64 t, %1; cvt.u32.u64 %0, t; }"
                 : "=r"(a) : "l"(p));
    return a;
}
__device__ __forceinline__ void ldsm4(uint32_t* r, uint32_t addr) {
    asm volatile("ldmatrix.sync.aligned.m8n8.x4.shared.b16 {%0,%1,%2,%3}, [%4];"
                 : "=r"(r[0]), "=r"(r[1]), "=r"(r[2]), "=r"(r[3]) : "r"(addr));
}
__device__ __forceinline__ void mma16816(float* c, const uint32_t* a,
                                         uint32_t b0, uint32_t b1) {
    asm volatile("mma.sync.aligned.m16n8k16.row.col.f32.f16.f16.f32 "
                 "{%0,%1,%2,%3}, {%4,%5,%6,%7}, {%8,%9}, {%0,%1,%2,%3};"
                 : "+f"(c[0]), "+f"(c[1]), "+f"(c[2]), "+f"(c[3])
                 : "r"(a[0]), "r"(a[1]), "r"(a[2]), "r"(a[3]), "r"(b0), "r"(b1));
}
#define CPASYNC16(dst, src) \
    asm volatile("cp.async.cg.shared.global [%0], [%1], 16;" :: "r"(dst), "l"(src))
#define CPCOMMIT() asm volatile("cp.async.commit_group;" ::: "memory")
#define CPWAIT1()  asm volatile("cp.async.wait_group 1;" ::: "memory")
#define CPWAIT0()  asm volatile("cp.async.wait_group 0;" ::: "memory")

// ---------------- k_pw: PW[8000,768] = Pf @ W1bt^T ----------------
#define PW_PITCH 80
#define PW_STAGE (192 * PW_PITCH)
__global__ void __launch_bounds__(256, 1)
k_pw()
{
    __shared__ char smem[3 * PW_STAGE];
    const int tid   = threadIdx.x;
    const int lane  = tid & 31;
    const int wid   = tid >> 5;
    const int warpM = wid >> 2;
    const int warpN = wid & 3;
    const int m0    = blockIdx.x * 64;
    const int n0    = blockIdx.y * 128;
    const uint32_t tile_base = smem_u32(smem);
    const int r0 = tid >> 2;
    const int c0 = tid & 3;

    float acc[2][4][4];
#pragma unroll
    for (int mf = 0; mf < 2; ++mf)
#pragma unroll
        for (int nf = 0; nf < 4; ++nf)
#pragma unroll
            for (int q = 0; q < 4; ++q) acc[mf][nf][q] = 0.0f;

#pragma unroll
    for (int s = 0; s < 2; ++s) {
        const int k0 = s * 32;
        uint32_t sA = tile_base + s * PW_STAGE;
        uint32_t sB = sA + 64 * PW_PITCH;
        CPASYNC16(sA + r0 * PW_PITCH + c0 * 16,
                  (const void*)&g_Pf[(size_t)(m0 + r0) * KD_ + k0 + c0 * 8]);
        CPASYNC16(sB + r0 * PW_PITCH + c0 * 16,
                  (const void*)&g_W1bt[(size_t)(n0 + r0) * KD_ + k0 + c0 * 8]);
        CPASYNC16(sB + (r0 + 64) * PW_PITCH + c0 * 16,
                  (const void*)&g_W1bt[(size_t)(n0 + r0 + 64) * KD_ + k0 + c0 * 8]);
        CPCOMMIT();
    }

#pragma unroll 1
    for (int kt = 0; kt < 12; ++kt) {
        if (kt < 11) { CPWAIT1(); } else { CPWAIT0(); }
        __syncthreads();
        if (kt + 2 < 12) {
            const int k0 = (kt + 2) * 32;
            const int st = (kt + 2) % 3;
            uint32_t sA = tile_base + st * PW_STAGE;
            uint32_t sB = sA + 64 * PW_PITCH;
            CPASYNC16(sA + r0 * PW_PITCH + c0 * 16,
                      (const void*)&g_Pf[(size_t)(m0 + r0) * KD_ + k0 + c0 * 8]);
            CPASYNC16(sB + r0 * PW_PITCH + c0 * 16,
                      (const void*)&g_W1bt[(size_t)(n0 + r0) * KD_ + k0 + c0 * 8]);
            CPASYNC16(sB + (r0 + 64) * PW_PITCH + c0 * 16,
                      (const void*)&g_W1bt[(size_t)(n0 + r0 + 64) * KD_ + k0 + c0 * 8]);
            CPCOMMIT();
        }
        const int st = kt % 3;
        uint32_t sA = tile_base + st * PW_STAGE;
        uint32_t sB = sA + 64 * PW_PITCH;
#pragma unroll
        for (int ks = 0; ks < 2; ++ks) {
            uint32_t afr[2][4], bfr[2][4];
#pragma unroll
            for (int mf = 0; mf < 2; ++mf) {
                uint32_t addr = sA + (warpM * 32 + mf * 16 + (lane & 15)) * PW_PITCH
                                   + (ks * 2 + (lane >> 4)) * 16;
                ldsm4(afr[mf], addr);
            }
#pragma unroll
            for (int nq = 0; nq < 2; ++nq) {
                uint32_t addr = sB + (warpN * 32 + nq * 16 + (lane & 7) + ((lane >> 4) & 1) * 8) * PW_PITCH
                                   + (ks * 2 + ((lane >> 3) & 1)) * 16;
                ldsm4(bfr[nq], addr);
            }
#pragma unroll
            for (int mf = 0; mf < 2; ++mf)
#pragma unroll
                for (int nq = 0; nq < 2; ++nq) {
                    mma16816(acc[mf][nq * 2],     afr[mf], bfr[nq][0], bfr[nq][1]);
                    mma16816(acc[mf][nq * 2 + 1], afr[mf], bfr[nq][2], bfr[nq][3]);
                }
        }
    }
#pragma unroll
    for (int mf = 0; mf < 2; ++mf)
#pragma unroll
        for (int hr = 0; hr < 2; ++hr) {
            int row = m0 + warpM * 32 + mf * 16 + hr * 8 + (lane >> 2);
#pragma unroll
            for (int nf = 0; nf < 4; ++nf) {
                int col = n0 + warpN * 32 + nf * 8 + (lane & 3) * 2;
                __half2 h = __floats2half2_rn(acc[mf][nf][2 * hr], acc[mf][nf][2 * hr + 1]);
                *(__half2*)&g_PW[(size_t)row * HID_ + col] = h;
            }
        }
}

// ---------------- main GEMM: round-3 skeleton, K=384 + coalesced mean gather --------
// smem: W2 @0 (36864) | b1 @36864 (3072) | mean @39936 (32768: 128x128 fp16)
//       tiles @72704 (3 * 20480) => 134144 total; final reduce reuses mean area
#define SM_W2    0
#define SM_B1    36864
#define SM_MEAN  39936
#define SM_TILE  72704
#define STAGE_BYTES 20480
#define ROW_PITCH   80
#define SMEM_BYTES  134144

#define NT_   6
#define KT_   12                // 384 / 32
#define KTG_  (NT_ * KT_)       // 72

__global__ void __launch_bounds__(256, 1)
k_gemm(const float* __restrict__ b1, const float* __restrict__ W2,
       const float* __restrict__ b2, float* __restrict__ out)
{
    extern __shared__ char smem[];
    const int tid   = threadIdx.x;
    const int lane  = tid & 31;
    const int wid   = tid >> 5;
    const int warpM = wid >> 1;          // 0..3
    const int warpN = wid & 1;           // 0..1
    const int m0    = blockIdx.x * 128;

    float*  w2s = (float*)(smem + SM_W2);
    float*  b1s = (float*)(smem + SM_B1);
    __half* mns = (__half*)(smem + SM_MEAN);   // [128][128]
    const uint32_t tile_base = smem_u32(smem + SM_TILE);

    for (int i = tid; i < HID_ * H_; i += 256) w2s[i] = W2[i];
    for (int i = tid; i < HID_;      i += 256) b1s[i] = b1[i];
    __syncthreads();

    const int r0 = tid >> 2;             // 0..63
    const int c0 = tid & 3;

    float pers[4][3];
#pragma unroll
    for (int i = 0; i < 4; ++i)
#pragma unroll
        for (int j = 0; j < 3; ++j) pers[i][j] = 0.0f;

    float acc[2][8][4];
#pragma unroll
    for (int mf = 0; mf < 2; ++mf)
#pragma unroll
        for (int nf = 0; nf < 8; ++nf)
#pragma unroll
            for (int q = 0; q < 4; ++q) acc[mf][nf][q] = 0.0f;

    // ---- prologue: stages ktg = 0, 1 (nt=0) ----
#pragma unroll
    for (int s = 0; s < 2; ++s) {
        const int k0 = s * 32;
        uint32_t sA = tile_base + s * STAGE_BYTES;
        uint32_t sB = sA + 128 * ROW_PITCH;
#pragma unroll
        for (int it = 0; it < 2; ++it) {
            int r = r0 + it * 64;
            CPASYNC16(sA + r * ROW_PITCH + c0 * 16,
                      (const void*)&g_X[(size_t)(m0 + r) * KD_ + k0 + c0 * 8]);
            CPASYNC16(sB + r * ROW_PITCH + c0 * 16,
                      (const void*)&g_W1t[(size_t)r * KD_ + k0 + c0 * 8]);
        }
        CPCOMMIT();
    }

    // ---- continuous mainloop: 72 iterations ----
#pragma unroll 1
    for (int ktg = 0; ktg < KTG_; ++ktg) {
        if (ktg < KTG_ - 1) { CPWAIT1(); } else { CPWAIT0(); }
        __syncthreads();

        if (ktg + 2 < KTG_) {
            const int pg  = ktg + 2;
            const int pk0 = (pg % KT_) * 32;
            const int pn0 = (pg / KT_) * 128;
            const int st  = pg % 3;
            uint32_t sA = tile_base + st * STAGE_BYTES;
            uint32_t sB = sA + 128 * ROW_PITCH;
#pragma unroll
            for (int it = 0; it < 2; ++it) {
                int r = r0 + it * 64;
                CPASYNC16(sA + r * ROW_PITCH + c0 * 16,
                          (const void*)&g_X[(size_t)(m0 + r) * KD_ + pk0 + c0 * 8]);
                CPASYNC16(sB + r * ROW_PITCH + c0 * 16,
                          (const void*)&g_W1t[(size_t)(pn0 + r) * KD_ + pk0 + c0 * 8]);
            }
            CPCOMMIT();
        }

        // ---- compute current stage ----
        {
            const int st = ktg % 3;
            uint32_t sA = tile_base + st * STAGE_BYTES;
            uint32_t sB = sA + 128 * ROW_PITCH;
#pragma unroll
            for (int ks = 0; ks < 2; ++ks) {
                uint32_t afr[2][4], bfr[4][4];
#pragma unroll
                for (int mf = 0; mf < 2; ++mf) {
                    uint32_t addr = sA + (warpM * 32 + mf * 16 + (lane & 15)) * ROW_PITCH
                                       + (ks * 2 + (lane >> 4)) * 16;
                    ldsm4(afr[mf], addr);
                }
#pragma unroll
                for (int nq = 0; nq < 4; ++nq) {
                    uint32_t addr = sB + (warpN * 64 + nq * 16 + (lane & 7) + ((lane >> 4) & 1) * 8) * ROW_PITCH
                                       + (ks * 2 + ((lane >> 3) & 1)) * 16;
                    ldsm4(bfr[nq], addr);
                }
#pragma unroll
                for (int mf = 0; mf < 2; ++mf)
#pragma unroll
                    for (int nq = 0; nq < 4; ++nq) {
                        mma16816(acc[mf][nq * 2],     afr[mf], bfr[nq][0], bfr[nq][1]);
                        mma16816(acc[mf][nq * 2 + 1], afr[mf], bfr[nq][2], bfr[nq][3]);
                    }
            }
        }

        // ---- n-tile boundary: coalesced mean gather + fused epilogue ----
        if ((ktg % KT_) == (KT_ - 1)) {
            const int n0 = (ktg / KT_) * 128;

            // cooperative gather: warp wid covers rows wid*16..+15; lane covers 4 cols (8B)
#pragma unroll 1
            for (int j = 0; j < 16; ++j) {
                int r  = wid * 16 + j;
                int m  = m0 + r;
                int bb = m / N_;
                int nn = m - bb * N_;
                int eb = g_off[nn];
                int ec = g_off[nn + 1] - eb;
                float inv = 1.0f / fmaxf((float)ec, 1.0f);
                float fs0 = 0.f, fs1 = 0.f, fs2 = 0.f, fs3 = 0.f;
                for (int e = 0; e < ec; ++e) {
                    int pp = g_edgep[eb + e];
                    uint2 v = *(const uint2*)&g_PW[((size_t)(bb * P_ + pp)) * HID_ + n0 + lane * 4];
                    union { uint2 u; __half2 h[2]; } cv; cv.u = v;
                    float2 f0 = __half22float2(cv.h[0]);
                    float2 f1 = __half22float2(cv.h[1]);
                    fs0 += f0.x; fs1 += f0.y; fs2 += f1.x; fs3 += f1.y;
                }
                union { uint2 u; __half2 h[2]; } ov;
                ov.h[0] = __floats2half2_rn(fs0 * inv, fs1 * inv);
                ov.h[1] = __floats2half2_rn(fs2 * inv, fs3 * inv);
                *(uint2*)&mns[r * 128 + lane * 4] = ov.u;
            }
            __syncthreads();

            // epilogue: acc + mean + b1, relu, fold GEMM2 into pers
#pragma unroll
            for (int mf = 0; mf < 2; ++mf) {
#pragma unroll
                for (int hr = 0; hr < 2; ++hr) {
                    const int rowL = warpM * 32 + mf * 16 + hr * 8 + (lane >> 2);
                    float p[12];
#pragma unroll
                    for (int o = 0; o < 12; ++o) p[o] = 0.0f;
#pragma unroll
                    for (int nf = 0; nf < 8; ++nf) {
                        int cl   = warpN * 64 + nf * 8 + (lane & 3) * 2;
                        int col0 = n0 + cl;
                        float2 mf2 = __half22float2(*(const __half2*)&mns[rowL * 128 + cl]);
                        float v0 = fmaxf(acc[mf][nf][2 * hr]     + mf2.x + b1s[col0],     0.0f);
                        float v1 = fmaxf(acc[mf][nf][2 * hr + 1] + mf2.y + b1s[col0 + 1], 0.0f);
                        const float4* wp0 = (const float4*)(w2s + col0 * 12);
                        const float4* wp1 = (const float4*)(w2s + (col0 + 1) * 12);
                        float4 a0 = wp0[0], a1 = wp0[1], a2 = wp0[2];
                        float4 d0 = wp1[0], d1 = wp1[1], d2 = wp1[2];
                        p[0]  += v0 * a0.x + v1 * d0.x;  p[1]  += v0 * a0.y + v1 * d0.y;
                        p[2]  += v0 * a0.z + v1 * d0.z;  p[3]  += v0 * a0.w + v1 * d0.w;
                        p[4]  += v0 * a1.x + v1 * d1.x;  p[5]  += v0 * a1.y + v1 * d1.y;
                        p[6]  += v0 * a1.z + v1 * d1.z;  p[7]  += v0 * a1.w + v1 * d1.w;
                        p[8]  += v0 * a2.x + v1 * d2.x;  p[9]  += v0 * a2.y + v1 * d2.y;
                        p[10] += v0 * a2.z + v1 * d2.z;  p[11] += v0 * a2.w + v1 * d2.w;
                    }
#pragma unroll
                    for (int o = 0; o < 12; ++o) {
                        p[o] += __shfl_xor_sync(0xffffffffu, p[o], 1);
                        p[o] += __shfl_xor_sync(0xffffffffu, p[o], 2);
                    }
                    int q = lane & 3;
                    pers[mf * 2 + hr][0] += p[3 * q + 0];
                    pers[mf * 2 + hr][1] += p[3 * q + 1];
                    pers[mf * 2 + hr][2] += p[3 * q + 2];
                }
            }
#pragma unroll
            for (int mf = 0; mf < 2; ++mf)
#pragma unroll
                for (int nf = 0; nf < 8; ++nf)
#pragma unroll
                    for (int q = 0; q < 4; ++q) acc[mf][nf][q] = 0.0f;
            __syncthreads();   // mean buffer reuse next boundary
        }
    }

    // ---- cross-warpN reduce (reuse mean area), then global write ----
    float* red = (float*)(smem + SM_MEAN);
    __syncthreads();
    if (warpN == 1) {
#pragma unroll
        for (int i = 0; i < 4; ++i) {
            int mf = i >> 1, hr = i & 1;
            int rowL = warpM * 32 + mf * 16 + hr * 8 + (lane >> 2);
            int q = lane & 3;
#pragma unroll
            for (int j = 0; j < 3; ++j)
                red[rowL * 12 + 3 * q + j] = pers[i][j];
        }
    }
    __syncthreads();
    if (warpN == 0) {
#pragma unroll
        for (int i = 0; i < 4; ++i) {
            int mf = i >> 1, hr = i & 1;
            int rowL = warpM * 32 + mf * 16 + hr * 8 + (lane >> 2);
            int q = lane & 3;
            size_t row = (size_t)(m0 + rowL);
#pragma unroll
            for (int j = 0; j < 3; ++j) {
                int o = 3 * q + j;
                out[row * 12 + o] = pers[i][j] + red[rowL * 12 + o] + b2[o];
            }
        }
    }
}

// ---------------- launch ----------------
extern "C" void kernel_launch(void* const* d_in, const int* in_sizes, int n_in,
                              void* d_out, int out_size)
{
    const float* patch  = (const float*)d_in[0];
    const float* nodes  = (const float*)d_in[1];
    const int*   batch  = (const int*)d_in[2];
    const int*   mapper = (const int*)d_in[3];
    const float* W1     = (const float*)d_in[4];
    const float* b1     = (const float*)d_in[5];
    const float* W2     = (const float*)d_in[6];
    const float* b2     = (const float*)d_in[7];
    float*       out    = (float*)d_out;

    k_conv<<<(W1T_WORK + NX_WORK + PF_WORK + 255) / 256, 256>>>(W1, nodes, patch);  // 0
    dim3 pwgrid(BP_ / 64, HID_ / 128);
    k_pw<<<pwgrid, 256>>>();                                                        // 1
    cudaFuncSetAttribute(k_csr, cudaFuncAttributeMaxDynamicSharedMemorySize, N_ * 4);
    k_csr<<<1, 1024, N_ * 4>>>(mapper, batch);                                      // 2
    cudaFuncSetAttribute(k_gemm, cudaFuncAttributeMaxDynamicSharedMemorySize, SMEM_BYTES);
    k_gemm<<<M_ / 128, 256, SMEM_BYTES>>>(b1, W2, b2, out);                         // 3
}

// round 9
// speedup vs baseline: 1.8605x; 1.3422x over previous
#include <cuda_runtime.h>
#include <cuda_fp16.h>
#include <cstdint>
#include <cstddef>

// ---------------- problem constants ----------------
#define B_   8
#define T_   12
#define P_   1000
#define N_   20000
#define E_   60000
#define FP_  32
#define FN_  32
#define H_   12
#define KD_  384                 // GEMM1 K after PW split
#define HID_ 768
#define M_   (B_ * N_)           // 160000 rows
#define BP_  (B_ * P_)           // 8000 distinct patch rows

// ---------------- device scratch ----------------
__device__ __half g_X[(size_t)M_ * KD_];
__device__ __half g_W1t[HID_ * KD_];        // W1 top half transposed
__device__ __half g_W1bt[HID_ * KD_];       // W1 bottom half transposed
__device__ __half g_Pf[BP_ * KD_];
__device__ __half g_PW[(size_t)BP_ * HID_];
__device__ __half g_MX[(size_t)M_ * HID_];  // per-row mean of PW rows (written/read by k_gemm)
__device__ int    g_off[N_ + 1];
__device__ int    g_edgep[E_];

// ---------------- fused conversions ----------------
#define W1T_WORK (HID_ * HID_)
#define NX_WORK  (B_ * T_ * N_ * 4)
#define PF_WORK  (B_ * T_ * P_ * 4)
__global__ void k_conv(const float* __restrict__ W1, const float* __restrict__ nodes_x,
                       const float* __restrict__ patch) {
    int i = blockIdx.x * blockDim.x + threadIdx.x;
    if (i < W1T_WORK) {
        int k = i / HID_, h = i % HID_;
        __half v = __float2half_rn(W1[i]);
        if (k < KD_) g_W1t[h * KD_ + k] = v;
        else         g_W1bt[h * KD_ + (k - KD_)] = v;
    } else if (i < W1T_WORK + NX_WORK) {
        int j = i - W1T_WORK;
        int q  = j & 3;
        int n  = (j >> 2) % N_;
        int bt = (j >> 2) / N_;
        int b = bt / T_, t = bt % T_;
        const float4* src = (const float4*)(nodes_x + ((size_t)bt * N_ + n) * FN_ + q * 8);
        float4 a = src[0], c = src[1];
        union { __half2 h[4]; uint4 u; } cv;
        cv.h[0] = __floats2half2_rn(a.x, a.y);
        cv.h[1] = __floats2half2_rn(a.z, a.w);
        cv.h[2] = __floats2half2_rn(c.x, c.y);
        cv.h[3] = __floats2half2_rn(c.z, c.w);
        *(uint4*)&g_X[((size_t)(b * N_ + n)) * KD_ + t * FN_ + q * 8] = cv.u;
    } else if (i < W1T_WORK + NX_WORK + PF_WORK) {
        int j = i - W1T_WORK - NX_WORK;
        int q  = j & 3;
        int p  = (j >> 2) % P_;
        int bt = (j >> 2) / P_;
        int b = bt / T_, t = bt % T_;
        const float4* src = (const float4*)(patch + ((size_t)bt * P_ + p) * FP_ + q * 8);
        float4 a = src[0], c = src[1];
        union { __half2 h[4]; uint4 u; } cv;
        cv.h[0] = __floats2half2_rn(a.x, a.y);
        cv.h[1] = __floats2half2_rn(a.z, a.w);
        cv.h[2] = __floats2half2_rn(c.x, c.y);
        cv.h[3] = __floats2half2_rn(c.z, c.w);
        *(uint4*)&g_Pf[((size_t)(b * P_ + p)) * KD_ + t * FP_ + q * 8] = cv.u;
    }
}

// ---------------- single-block CSR build ----------------
__global__ void k_csr(const int* __restrict__ mapper, const int* __restrict__ batch) {
    extern __shared__ int scnt[];
    __shared__ int buf[1024];
    __shared__ int carry;
    int t = threadIdx.x;
    for (int i = t; i < N_; i += 1024) scnt[i] = 0;
    __syncthreads();
    for (int e = t; e < E_; e += 1024) atomicAdd(&scnt[mapper[e]], 1);
    __syncthreads();
    if (t == 0) { carry = 0; g_off[0] = 0; }
    __syncthreads();
    for (int base = 0; base < N_; base += 1024) {
        int i = base + t;
        int v = (i < N_) ? scnt[i] : 0;
        buf[t] = v;
        __syncthreads();
        for (int s = 1; s < 1024; s <<= 1) {
            int add = (t >= s) ? buf[t - s] : 0;
            __syncthreads();
            buf[t] += add;
            __syncthreads();
        }
        int incl = buf[t] + carry;
        if (i < N_) { g_off[i + 1] = incl; scnt[i] = incl - v; }
        __syncthreads();
        if (t == 1023) carry = incl;
        __syncthreads();
    }
    for (int e = t; e < E_; e += 1024) {
        int n = mapper[e];
        int idx = atomicAdd(&scnt[n], 1);
        g_edgep[idx] = batch[e];
    }
}

// ---------------- mma helpers ----------------
__device__ __forceinline__ uint32_t smem_u32(const void* p) {
    uint32_t a;
    asm volatile("{ .reg .u64 t; cvta.to.shared.u64 t, %1; cvt.u32.u64 %0, t; }"
                 : "=r"(a) : "l"(p));
    return a;
}
__device__ __forceinline__ void ldsm4(uint32_t* r, uint32_t addr) {
    asm volatile("ldmatrix.sync.aligned.m8n8.x4.shared.b16 {%0,%1,%2,%3}, [%4];"
                 : "=r"(r[0]), "=r"(r[1]), "=r"(r[2]), "=r"(r[3]) : "r"(addr));
}
__device__ __forceinline__ void mma16816(float* c, const uint32_t* a,
                                         uint32_t b0, uint32_t b1) {
    asm volatile("mma.sync.aligned.m16n8k16.row.col.f32.f16.f16.f32 "
                 "{%0,%1,%2,%3}, {%4,%5,%6,%7}, {%8,%9}, {%0,%1,%2,%3};"
                 : "+f"(c[0]), "+f"(c[1]), "+f"(c[2]), "+f"(c[3])
                 : "r"(a[0]), "r"(a[1]), "r"(a[2]), "r"(a[3]), "r"(b0), "r"(b1));
}
#define CPASYNC16(dst, src) \
    asm volatile("cp.async.cg.shared.global [%0], [%1], 16;" :: "r"(dst), "l"(src))
#define CPCOMMIT() asm volatile("cp.async.commit_group;" ::: "memory")
#define CPWAIT1()  asm volatile("cp.async.wait_group 1;" ::: "memory")
#define CPWAIT0()  asm volatile("cp.async.wait_group 0;" ::: "memory")

// ---------------- k_pw: PW[8000,768] = Pf @ W1bt^T ----------------
#define PW_PITCH 80
#define PW_STAGE (192 * PW_PITCH)
__global__ void __launch_bounds__(256, 1)
k_pw()
{
    __shared__ char smem[3 * PW_STAGE];
    const int tid   = threadIdx.x;
    const int lane  = tid & 31;
    const int wid   = tid >> 5;
    const int warpM = wid >> 2;
    const int warpN = wid & 3;
    const int m0    = blockIdx.x * 64;
    const int n0    = blockIdx.y * 128;
    const uint32_t tile_base = smem_u32(smem);
    const int r0 = tid >> 2;
    const int c0 = tid & 3;

    float acc[2][4][4];
#pragma unroll
    for (int mf = 0; mf < 2; ++mf)
#pragma unroll
        for (int nf = 0; nf < 4; ++nf)
#pragma unroll
            for (int q = 0; q < 4; ++q) acc[mf][nf][q] = 0.0f;

#pragma unroll
    for (int s = 0; s < 2; ++s) {
        const int k0 = s * 32;
        uint32_t sA = tile_base + s * PW_STAGE;
        uint32_t sB = sA + 64 * PW_PITCH;
        CPASYNC16(sA + r0 * PW_PITCH + c0 * 16,
                  (const void*)&g_Pf[(size_t)(m0 + r0) * KD_ + k0 + c0 * 8]);
        CPASYNC16(sB + r0 * PW_PITCH + c0 * 16,
                  (const void*)&g_W1bt[(size_t)(n0 + r0) * KD_ + k0 + c0 * 8]);
        CPASYNC16(sB + (r0 + 64) * PW_PITCH + c0 * 16,
                  (const void*)&g_W1bt[(size_t)(n0 + r0 + 64) * KD_ + k0 + c0 * 8]);
        CPCOMMIT();
    }

#pragma unroll 1
    for (int kt = 0; kt < 12; ++kt) {
        if (kt < 11) { CPWAIT1(); } else { CPWAIT0(); }
        __syncthreads();
        if (kt + 2 < 12) {
            const int k0 = (kt + 2) * 32;
            const int st = (kt + 2) % 3;
            uint32_t sA = tile_base + st * PW_STAGE;
            uint32_t sB = sA + 64 * PW_PITCH;
            CPASYNC16(sA + r0 * PW_PITCH + c0 * 16,
                      (const void*)&g_Pf[(size_t)(m0 + r0) * KD_ + k0 + c0 * 8]);
            CPASYNC16(sB + r0 * PW_PITCH + c0 * 16,
                      (const void*)&g_W1bt[(size_t)(n0 + r0) * KD_ + k0 + c0 * 8]);
            CPASYNC16(sB + (r0 + 64) * PW_PITCH + c0 * 16,
                      (const void*)&g_W1bt[(size_t)(n0 + r0 + 64) * KD_ + k0 + c0 * 8]);
            CPCOMMIT();
        }
        const int st = kt % 3;
        uint32_t sA = tile_base + st * PW_STAGE;
        uint32_t sB = sA + 64 * PW_PITCH;
#pragma unroll
        for (int ks = 0; ks < 2; ++ks) {
            uint32_t afr[2][4], bfr[2][4];
#pragma unroll
            for (int mf = 0; mf < 2; ++mf) {
                uint32_t addr = sA + (warpM * 32 + mf * 16 + (lane & 15)) * PW_PITCH
                                   + (ks * 2 + (lane >> 4)) * 16;
                ldsm4(afr[mf], addr);
            }
#pragma unroll
            for (int nq = 0; nq < 2; ++nq) {
                uint32_t addr = sB + (warpN * 32 + nq * 16 + (lane & 7) + ((lane >> 4) & 1) * 8) * PW_PITCH
                                   + (ks * 2 + ((lane >> 3) & 1)) * 16;
                ldsm4(bfr[nq], addr);
            }
#pragma unroll
            for (int mf = 0; mf < 2; ++mf)
#pragma unroll
                for (int nq = 0; nq < 2; ++nq) {
                    mma16816(acc[mf][nq * 2],     afr[mf], bfr[nq][0], bfr[nq][1]);
                    mma16816(acc[mf][nq * 2 + 1], afr[mf], bfr[nq][2], bfr[nq][3]);
                }
        }
    }
#pragma unroll
    for (int mf = 0; mf < 2; ++mf)
#pragma unroll
        for (int hr = 0; hr < 2; ++hr) {
            int row = m0 + warpM * 32 + mf * 16 + hr * 8 + (lane >> 2);
#pragma unroll
            for (int nf = 0; nf < 4; ++nf) {
                int col = n0 + warpN * 32 + nf * 8 + (lane & 3) * 2;
                __half2 h = __floats2half2_rn(acc[mf][nf][2 * hr], acc[mf][nf][2 * hr + 1]);
                *(__half2*)&g_PW[(size_t)row * HID_ + col] = h;
            }
        }
}

// ---------------- main GEMM: CTA 128x64, warp 32x32, 2 CTAs/SM -------------------
// smem: W2 @0 (36864) | b1 @36864 (3072) | tiles @39936: 3 * (128+64)*80 = 46080
//       => 86016 total; final reduce reuses tile area
#define SM_W2    0
#define SM_B1    36864
#define SM_TILE  39936
#define ROW_PITCH   80
#define STAGE_BYTES ((128 + 64) * ROW_PITCH)   // 15360
#define SMEM_BYTES  86016

#define NT_   12
#define KT_   12                // 384 / 32
#define KTG_  (NT_ * KT_)       // 144

__global__ void __launch_bounds__(256, 2)
k_gemm(const float* __restrict__ b1, const float* __restrict__ W2,
       const float* __restrict__ b2, float* __restrict__ out)
{
    extern __shared__ char smem[];
    const int tid   = threadIdx.x;
    const int lane  = tid & 31;
    const int wid   = tid >> 5;
    const int warpM = wid >> 1;          // 0..3
    const int warpN = wid & 1;           // 0..1
    const int m0    = blockIdx.x * 128;

    float* w2s = (float*)(smem + SM_W2);
    float* b1s = (float*)(smem + SM_B1);
    const uint32_t tile_base = smem_u32(smem + SM_TILE);

    for (int i = tid; i < HID_ * H_; i += 256) w2s[i] = W2[i];
    for (int i = tid; i < HID_;      i += 256) b1s[i] = b1[i];

    // ---- one-time mean gather for this CTA's 128 rows -> g_MX slice ----
    // warp wid handles rows wid*16..+15; lane covers 24 fp16 (3x uint4) of 768 cols
#pragma unroll 1
    for (int j = 0; j < 16; ++j) {
        int r  = wid * 16 + j;
        int m  = m0 + r;
        int bb = m / N_;
        int nn = m - bb * N_;
        int eb = g_off[nn];
        int ec = g_off[nn + 1] - eb;
        float inv = 1.0f / fmaxf((float)ec, 1.0f);
        float fs[24];
#pragma unroll
        for (int o = 0; o < 24; ++o) fs[o] = 0.0f;
        for (int e = 0; e < ec; ++e) {
            int pp = g_edgep[eb + e];
            const uint4* pr = (const uint4*)&g_PW[((size_t)(bb * P_ + pp)) * HID_];
#pragma unroll
            for (int u = 0; u < 3; ++u) {
                union { uint4 v; __half2 h[4]; } cv;
                cv.v = pr[lane + 32 * u];
#pragma unroll
                for (int o = 0; o < 4; ++o) {
                    float2 f = __half22float2(cv.h[o]);
                    fs[u * 8 + o * 2]     += f.x;
                    fs[u * 8 + o * 2 + 1] += f.y;
                }
            }
        }
        uint4* dst = (uint4*)&g_MX[(size_t)m * HID_];
#pragma unroll
        for (int u = 0; u < 3; ++u) {
            union { uint4 v; __half2 h[4]; } ov;
#pragma unroll
            for (int o = 0; o < 4; ++o)
                ov.h[o] = __floats2half2_rn(fs[u * 8 + o * 2] * inv, fs[u * 8 + o * 2 + 1] * inv);
            dst[lane + 32 * u] = ov.v;
        }
    }
    __syncthreads();   // g_MX slice + w2s/b1s visible to whole CTA

    const int r0 = tid >> 2;             // A rows 0..63 (x2), B rows 0..63
    const int c0 = tid & 3;

    float pers[4][3];
#pragma unroll
    for (int i = 0; i < 4; ++i)
#pragma unroll
        for (int j = 0; j < 3; ++j) pers[i][j] = 0.0f;

    float acc[2][4][4];
#pragma unroll
    for (int mf = 0; mf < 2; ++mf)
#pragma unroll
        for (int nf = 0; nf < 4; ++nf)
#pragma unroll
            for (int q = 0; q < 4; ++q) acc[mf][nf][q] = 0.0f;

    // ---- prologue: stages ktg = 0, 1 (nt=0) ----
#pragma unroll
    for (int s = 0; s < 2; ++s) {
        const int k0 = s * 32;
        uint32_t sA = tile_base + s * STAGE_BYTES;
        uint32_t sB = sA + 128 * ROW_PITCH;
#pragma unroll
        for (int it = 0; it < 2; ++it) {
            int r = r0 + it * 64;
            CPASYNC16(sA + r * ROW_PITCH + c0 * 16,
                      (const void*)&g_X[(size_t)(m0 + r) * KD_ + k0 + c0 * 8]);
        }
        CPASYNC16(sB + r0 * ROW_PITCH + c0 * 16,
                  (const void*)&g_W1t[(size_t)r0 * KD_ + k0 + c0 * 8]);
        CPCOMMIT();
    }

    // ---- continuous mainloop: 144 iterations ----
#pragma unroll 1
    for (int ktg = 0; ktg < KTG_; ++ktg) {
        if (ktg < KTG_ - 1) { CPWAIT1(); } else { CPWAIT0(); }
        __syncthreads();

        if (ktg + 2 < KTG_) {
            const int pg  = ktg + 2;
            const int pk0 = (pg % KT_) * 32;
            const int pn0 = (pg / KT_) * 64;
            const int st  = pg % 3;
            uint32_t sA = tile_base + st * STAGE_BYTES;
            uint32_t sB = sA + 128 * ROW_PITCH;
#pragma unroll
            for (int it = 0; it < 2; ++it) {
                int r = r0 + it * 64;
                CPASYNC16(sA + r * ROW_PITCH + c0 * 16,
                          (const void*)&g_X[(size_t)(m0 + r) * KD_ + pk0 + c0 * 8]);
            }
            CPASYNC16(sB + r0 * ROW_PITCH + c0 * 16,
                      (const void*)&g_W1t[(size_t)(pn0 + r0) * KD_ + pk0 + c0 * 8]);
            CPCOMMIT();
        }

        // ---- compute current stage ----
        {
            const int st = ktg % 3;
            uint32_t sA = tile_base + st * STAGE_BYTES;
            uint32_t sB = sA + 128 * ROW_PITCH;
#pragma unroll
            for (int ks = 0; ks < 2; ++ks) {
                uint32_t afr[2][4], bfr[2][4];
#pragma unroll
                for (int mf = 0; mf < 2; ++mf) {
                    uint32_t addr = sA + (warpM * 32 + mf * 16 + (lane & 15)) * ROW_PITCH
                                       + (ks * 2 + (lane >> 4)) * 16;
                    ldsm4(afr[mf], addr);
                }
#pragma unroll
                for (int nq = 0; nq < 2; ++nq) {
                    uint32_t addr = sB + (warpN * 32 + nq * 16 + (lane & 7) + ((lane >> 4) & 1) * 8) * ROW_PITCH
                                       + (ks * 2 + ((lane >> 3) & 1)) * 16;
                    ldsm4(bfr[nq], addr);
                }
#pragma unroll
                for (int mf = 0; mf < 2; ++mf)
#pragma unroll
                    for (int nq = 0; nq < 2; ++nq) {
                        mma16816(acc[mf][nq * 2],     afr[mf], bfr[nq][0], bfr[nq][1]);
                        mma16816(acc[mf][nq * 2 + 1], afr[mf], bfr[nq][2], bfr[nq][3]);
                    }
            }
        }

        // ---- n-tile boundary: prefetch mean, fused epilogue ----
        if ((ktg % KT_) == (KT_ - 1)) {
            const int n0 = (ktg / KT_) * 64;
#pragma unroll
            for (int mf = 0; mf < 2; ++mf) {
#pragma unroll
                for (int hr = 0; hr < 2; ++hr) {
                    const int rowL = warpM * 32 + mf * 16 + hr * 8 + (lane >> 2);
                    const size_t mrow = (size_t)(m0 + rowL) * HID_;
                    // prefetch all 4 mean half2's (independent loads)
                    __half2 mh[4];
#pragma unroll
                    for (int nf = 0; nf < 4; ++nf)
                        mh[nf] = *(const __half2*)&g_MX[mrow + n0 + warpN * 32 + nf * 8 + (lane & 3) * 2];

                    float p[12];
#pragma unroll
                    for (int o = 0; o < 12; ++o) p[o] = 0.0f;
#pragma unroll
                    for (int nf = 0; nf < 4; ++nf) {
                        int col0 = n0 + warpN * 32 + nf * 8 + (lane & 3) * 2;
                        float2 mf2 = __half22float2(mh[nf]);
                        float v0 = fmaxf(acc[mf][nf][2 * hr]     + mf2.x + b1s[col0],     0.0f);
                        float v1 = fmaxf(acc[mf][nf][2 * hr + 1] + mf2.y + b1s[col0 + 1], 0.0f);
                        const float4* wp0 = (const float4*)(w2s + col0 * 12);
                        const float4* wp1 = (const float4*)(w2s + (col0 + 1) * 12);
                        float4 a0 = wp0[0], a1 = wp0[1], a2 = wp0[2];
                        float4 d0 = wp1[0], d1 = wp1[1], d2 = wp1[2];
                        p[0]  += v0 * a0.x + v1 * d0.x;  p[1]  += v0 * a0.y + v1 * d0.y;
                        p[2]  += v0 * a0.z + v1 * d0.z;  p[3]  += v0 * a0.w + v1 * d0.w;
                        p[4]  += v0 * a1.x + v1 * d1.x;  p[5]  += v0 * a1.y + v1 * d1.y;
                        p[6]  += v0 * a1.z + v1 * d1.z;  p[7]  += v0 * a1.w + v1 * d1.w;
                        p[8]  += v0 * a2.x + v1 * d2.x;  p[9]  += v0 * a2.y + v1 * d2.y;
                        p[10] += v0 * a2.z + v1 * d2.z;  p[11] += v0 * a2.w + v1 * d2.w;
                    }
#pragma unroll
                    for (int o = 0; o < 12; ++o) {
                        p[o] += __shfl_xor_sync(0xffffffffu, p[o], 1);
                        p[o] += __shfl_xor_sync(0xffffffffu, p[o], 2);
                    }
                    int q = lane & 3;
                    pers[mf * 2 + hr][0] += p[3 * q + 0];
                    pers[mf * 2 + hr][1] += p[3 * q + 1];
                    pers[mf * 2 + hr][2] += p[3 * q + 2];
                }
            }
#pragma unroll
            for (int mf = 0; mf < 2; ++mf)
#pragma unroll
                for (int nf = 0; nf < 4; ++nf)
#pragma unroll
                    for (int q = 0; q < 4; ++q) acc[mf][nf][q] = 0.0f;
        }
    }

    // ---- cross-warpN reduce (reuse tile area), then global write ----
    float* red = (float*)(smem + SM_TILE);
    __syncthreads();
    if (warpN == 1) {
#pragma unroll
        for (int i = 0; i < 4; ++i) {
            int mf = i >> 1, hr = i & 1;
            int rowL = warpM * 32 + mf * 16 + hr * 8 + (lane >> 2);
            int q = lane & 3;
#pragma unroll
            for (int j = 0; j < 3; ++j)
                red[rowL * 12 + 3 * q + j] = pers[i][j];
        }
    }
    __syncthreads();
    if (warpN == 0) {
#pragma unroll
        for (int i = 0; i < 4; ++i) {
            int mf = i >> 1, hr = i & 1;
            int rowL = warpM * 32 + mf * 16 + hr * 8 + (lane >> 2);
            int q = lane & 3;
            size_t row = (size_t)(m0 + rowL);
#pragma unroll
            for (int j = 0; j < 3; ++j) {
                int o = 3 * q + j;
                out[row * 12 + o] = pers[i][j] + red[rowL * 12 + o] + b2[o];
            }
        }
    }
}

// ---------------- launch ----------------
extern "C" void kernel_launch(void* const* d_in, const int* in_sizes, int n_in,
                              void* d_out, int out_size)
{
    const float* patch  = (const float*)d_in[0];
    const float* nodes  = (const float*)d_in[1];
    const int*   batch  = (const int*)d_in[2];
    const int*   mapper = (const int*)d_in[3];
    const float* W1     = (const float*)d_in[4];
    const float* b1     = (const float*)d_in[5];
    const float* W2     = (const float*)d_in[6];
    const float* b2     = (const float*)d_in[7];
    float*       out    = (float*)d_out;

    k_conv<<<(W1T_WORK + NX_WORK + PF_WORK + 255) / 256, 256>>>(W1, nodes, patch);  // 0
    dim3 pwgrid(BP_ / 64, HID_ / 128);
    k_pw<<<pwgrid, 256>>>();                                                        // 1
    cudaFuncSetAttribute(k_csr, cudaFuncAttributeMaxDynamicSharedMemorySize, N_ * 4);
    k_csr<<<1, 1024, N_ * 4>>>(mapper, batch);                                      // 2
    cudaFuncSetAttribute(k_gemm, cudaFuncAttributeMaxDynamicSharedMemorySize, SMEM_BYTES);
    k_gemm<<<M_ / 128, 256, SMEM_BYTES>>>(b1, W2, b2, out);                         // 3
}

// round 10
// speedup vs baseline: 1.9720x; 1.0599x over previous
#include <cuda_runtime.h>
#include <cuda_fp16.h>
#include <cstdint>
#include <cstddef>

// ---------------- problem constants ----------------
#define B_   8
#define T_   12
#define P_   1000
#define N_   20000
#define E_   60000
#define FP_  32
#define FN_  32
#define H_   12
#define KD_  384                 // GEMM1 K after PW split
#define HID_ 768
#define M_   (B_ * N_)           // 160000 rows
#define BP_  (B_ * P_)           // 8000 distinct patch rows

// ---------------- device scratch ----------------
__device__ __half g_X[(size_t)M_ * KD_];
__device__ __half g_W1t[HID_ * KD_];        // W1 top half transposed
__device__ __half g_W1bt[HID_ * KD_];       // W1 bottom half transposed
__device__ __half g_Pf[BP_ * KD_];
__device__ __half g_PW[(size_t)BP_ * HID_];
__device__ __half g_MX[(size_t)M_ * HID_];  // per-row mean of PW rows
__device__ int    g_off[N_ + 1];
__device__ int    g_edgep[E_];

// ---------------- fused conversions ----------------
#define W1T_WORK (HID_ * HID_)
#define NX_WORK  (B_ * T_ * N_ * 4)
#define PF_WORK  (B_ * T_ * P_ * 4)
__global__ void k_conv(const float* __restrict__ W1, const float* __restrict__ nodes_x,
                       const float* __restrict__ patch) {
    int i = blockIdx.x * blockDim.x + threadIdx.x;
    if (i < W1T_WORK) {
        int k = i / HID_, h = i % HID_;
        __half v = __float2half_rn(W1[i]);
        if (k < KD_) g_W1t[h * KD_ + k] = v;
        else         g_W1bt[h * KD_ + (k - KD_)] = v;
    } else if (i < W1T_WORK + NX_WORK) {
        int j = i - W1T_WORK;
        int q  = j & 3;
        int n  = (j >> 2) % N_;
        int bt = (j >> 2) / N_;
        int b = bt / T_, t = bt % T_;
        const float4* src = (const float4*)(nodes_x + ((size_t)bt * N_ + n) * FN_ + q * 8);
        float4 a = src[0], c = src[1];
        union { __half2 h[4]; uint4 u; } cv;
        cv.h[0] = __floats2half2_rn(a.x, a.y);
        cv.h[1] = __floats2half2_rn(a.z, a.w);
        cv.h[2] = __floats2half2_rn(c.x, c.y);
        cv.h[3] = __floats2half2_rn(c.z, c.w);
        *(uint4*)&g_X[((size_t)(b * N_ + n)) * KD_ + t * FN_ + q * 8] = cv.u;
    } else if (i < W1T_WORK + NX_WORK + PF_WORK) {
        int j = i - W1T_WORK - NX_WORK;
        int q  = j & 3;
        int p  = (j >> 2) % P_;
        int bt = (j >> 2) / P_;
        int b = bt / T_, t = bt % T_;
        const float4* src = (const float4*)(patch + ((size_t)bt * P_ + p) * FP_ + q * 8);
        float4 a = src[0], c = src[1];
        union { __half2 h[4]; uint4 u; } cv;
        cv.h[0] = __floats2half2_rn(a.x, a.y);
        cv.h[1] = __floats2half2_rn(a.z, a.w);
        cv.h[2] = __floats2half2_rn(c.x, c.y);
        cv.h[3] = __floats2half2_rn(c.z, c.w);
        *(uint4*)&g_Pf[((size_t)(b * P_ + p)) * KD_ + t * FP_ + q * 8] = cv.u;
    }
}

// ---------------- single-block CSR build ----------------
__global__ void k_csr(const int* __restrict__ mapper, const int* __restrict__ batch) {
    extern __shared__ int scnt[];
    __shared__ int buf[1024];
    __shared__ int carry;
    int t = threadIdx.x;
    for (int i = t; i < N_; i += 1024) scnt[i] = 0;
    __syncthreads();
    for (int e = t; e < E_; e += 1024) atomicAdd(&scnt[mapper[e]], 1);
    __syncthreads();
    if (t == 0) { carry = 0; g_off[0] = 0; }
    __syncthreads();
    for (int base = 0; base < N_; base += 1024) {
        int i = base + t;
        int v = (i < N_) ? scnt[i] : 0;
        buf[t] = v;
        __syncthreads();
        for (int s = 1; s < 1024; s <<= 1) {
            int add = (t >= s) ? buf[t - s] : 0;
            __syncthreads();
            buf[t] += add;
            __syncthreads();
        }
        int incl = buf[t] + carry;
        if (i < N_) { g_off[i + 1] = incl; scnt[i] = incl - v; }
        __syncthreads();
        if (t == 1023) carry = incl;
        __syncthreads();
    }
    for (int e = t; e < E_; e += 1024) {
        int n = mapper[e];
        int idx = atomicAdd(&scnt[n], 1);
        g_edgep[idx] = batch[e];
    }
}

// ---------------- mma helpers ----------------
__device__ __forceinline__ uint32_t smem_u32(const void* p) {
    uint32_t a;
    asm volatile("{ .reg .u64 t; cvta.to.shared.u64 t, %1; cvt.u32.u64 %0, t; }"
                 : "=r"(a) : "l"(p));
    return a;
}
__device__ __forceinline__ void ldsm4(uint32_t* r, uint32_t addr) {
    asm volatile("ldmatrix.sync.aligned.m8n8.x4.shared.b16 {%0,%1,%2,%3}, [%4];"
                 : "=r"(r[0]), "=r"(r[1]), "=r"(r[2]), "=r"(r[3]) : "r"(addr));
}
__device__ __forceinline__ void mma16816(float* c, const uint32_t* a,
                                         uint32_t b0, uint32_t b1) {
    asm volatile("mma.sync.aligned.m16n8k16.row.col.f32.f16.f16.f32 "
                 "{%0,%1,%2,%3}, {%4,%5,%6,%7}, {%8,%9}, {%0,%1,%2,%3};"
                 : "+f"(c[0]), "+f"(c[1]), "+f"(c[2]), "+f"(c[3])
                 : "r"(a[0]), "r"(a[1]), "r"(a[2]), "r"(a[3]), "r"(b0), "r"(b1));
}
#define CPASYNC16(dst, src) \
    asm volatile("cp.async.cg.shared.global [%0], [%1], 16;" :: "r"(dst), "l"(src))
#define CPCOMMIT() asm volatile("cp.async.commit_group;" ::: "memory")
#define CPWAIT1()  asm volatile("cp.async.wait_group 1;" ::: "memory")
#define CPWAIT0()  asm volatile("cp.async.wait_group 0;" ::: "memory")

// ---------------- k_pw: PW[8000,768] = Pf @ W1bt^T ----------------
#define PW_PITCH 80
#define PW_STAGE (192 * PW_PITCH)
__global__ void __launch_bounds__(256, 1)
k_pw()
{
    __shared__ char smem[3 * PW_STAGE];
    const int tid   = threadIdx.x;
    const int lane  = tid & 31;
    const int wid   = tid >> 5;
    const int warpM = wid >> 2;
    const int warpN = wid & 3;
    const int m0    = blockIdx.x * 64;
    const int n0    = blockIdx.y * 128;
    const uint32_t tile_base = smem_u32(smem);
    const int r0 = tid >> 2;
    const int c0 = tid & 3;

    float acc[2][4][4];
#pragma unroll
    for (int mf = 0; mf < 2; ++mf)
#pragma unroll
        for (int nf = 0; nf < 4; ++nf)
#pragma unroll
            for (int q = 0; q < 4; ++q) acc[mf][nf][q] = 0.0f;

#pragma unroll
    for (int s = 0; s < 2; ++s) {
        const int k0 = s * 32;
        uint32_t sA = tile_base + s * PW_STAGE;
        uint32_t sB = sA + 64 * PW_PITCH;
        CPASYNC16(sA + r0 * PW_PITCH + c0 * 16,
                  (const void*)&g_Pf[(size_t)(m0 + r0) * KD_ + k0 + c0 * 8]);
        CPASYNC16(sB + r0 * PW_PITCH + c0 * 16,
                  (const void*)&g_W1bt[(size_t)(n0 + r0) * KD_ + k0 + c0 * 8]);
        CPASYNC16(sB + (r0 + 64) * PW_PITCH + c0 * 16,
                  (const void*)&g_W1bt[(size_t)(n0 + r0 + 64) * KD_ + k0 + c0 * 8]);
        CPCOMMIT();
    }

#pragma unroll 1
    for (int kt = 0; kt < 12; ++kt) {
        if (kt < 11) { CPWAIT1(); } else { CPWAIT0(); }
        __syncthreads();
        if (kt + 2 < 12) {
            const int k0 = (kt + 2) * 32;
            const int st = (kt + 2) % 3;
            uint32_t sA = tile_base + st * PW_STAGE;
            uint32_t sB = sA + 64 * PW_PITCH;
            CPASYNC16(sA + r0 * PW_PITCH + c0 * 16,
                      (const void*)&g_Pf[(size_t)(m0 + r0) * KD_ + k0 + c0 * 8]);
            CPASYNC16(sB + r0 * PW_PITCH + c0 * 16,
                      (const void*)&g_W1bt[(size_t)(n0 + r0) * KD_ + k0 + c0 * 8]);
            CPASYNC16(sB + (r0 + 64) * PW_PITCH + c0 * 16,
                      (const void*)&g_W1bt[(size_t)(n0 + r0 + 64) * KD_ + k0 + c0 * 8]);
            CPCOMMIT();
        }
        const int st = kt % 3;
        uint32_t sA = tile_base + st * PW_STAGE;
        uint32_t sB = sA + 64 * PW_PITCH;
#pragma unroll
        for (int ks = 0; ks < 2; ++ks) {
            uint32_t afr[2][4], bfr[2][4];
#pragma unroll
            for (int mf = 0; mf < 2; ++mf) {
                uint32_t addr = sA + (warpM * 32 + mf * 16 + (lane & 15)) * PW_PITCH
                                   + (ks * 2 + (lane >> 4)) * 16;
                ldsm4(afr[mf], addr);
            }
#pragma unroll
            for (int nq = 0; nq < 2; ++nq) {
                uint32_t addr = sB + (warpN * 32 + nq * 16 + (lane & 7) + ((lane >> 4) & 1) * 8) * PW_PITCH
                                   + (ks * 2 + ((lane >> 3) & 1)) * 16;
                ldsm4(bfr[nq], addr);
            }
#pragma unroll
            for (int mf = 0; mf < 2; ++mf)
#pragma unroll
                for (int nq = 0; nq < 2; ++nq) {
                    mma16816(acc[mf][nq * 2],     afr[mf], bfr[nq][0], bfr[nq][1]);
                    mma16816(acc[mf][nq * 2 + 1], afr[mf], bfr[nq][2], bfr[nq][3]);
                }
        }
    }
#pragma unroll
    for (int mf = 0; mf < 2; ++mf)
#pragma unroll
        for (int hr = 0; hr < 2; ++hr) {
            int row = m0 + warpM * 32 + mf * 16 + hr * 8 + (lane >> 2);
#pragma unroll
            for (int nf = 0; nf < 4; ++nf) {
                int col = n0 + warpN * 32 + nf * 8 + (lane & 3) * 2;
                __half2 h = __floats2half2_rn(acc[mf][nf][2 * hr], acc[mf][nf][2 * hr + 1]);
                *(__half2*)&g_PW[(size_t)row * HID_ + col] = h;
            }
        }
}

// ---------------- main GEMM: CTA 128x64, warp 32x32, pair-granular triple buffer ----
// smem: 3 pair-buffers * 2 stages * (128+64)*80 = 92160 bytes (nothing else)
#define ROW_PITCH   80
#define STAGE_BYTES ((128 + 64) * ROW_PITCH)   // 15360
#define PAIR_BYTES  (2 * STAGE_BYTES)          // 30720
#define SMEM_BYTES  (3 * PAIR_BYTES)           // 92160

#define NT_   12
#define KT_   12                // K-chunks of 32 per n-tile
#define IT_   72                // pairs total (144 stages / 2)

__global__ void __launch_bounds__(256, 2)
k_gemm(const float* __restrict__ b1, const float* __restrict__ W2,
       const float* __restrict__ b2, float* __restrict__ out)
{
    extern __shared__ char smem[];
    const int tid   = threadIdx.x;
    const int lane  = tid & 31;
    const int wid   = tid >> 5;
    const int warpM = wid >> 1;          // 0..3
    const int warpN = wid & 1;           // 0..1
    const int m0    = blockIdx.x * 128;
    const uint32_t tile_base = smem_u32(smem);

    // ---- one-time mean gather for this CTA's 128 rows -> g_MX slice ----
#pragma unroll 1
    for (int j = 0; j < 16; ++j) {
        int r  = wid * 16 + j;
        int m  = m0 + r;
        int bb = m / N_;
        int nn = m - bb * N_;
        int eb = g_off[nn];
        int ec = g_off[nn + 1] - eb;
        float inv = 1.0f / fmaxf((float)ec, 1.0f);
        float fs[24];
#pragma unroll
        for (int o = 0; o < 24; ++o) fs[o] = 0.0f;
        for (int e = 0; e < ec; ++e) {
            int pp = g_edgep[eb + e];
            const uint4* pr = (const uint4*)&g_PW[((size_t)(bb * P_ + pp)) * HID_];
#pragma unroll
            for (int u = 0; u < 3; ++u) {
                union { uint4 v; __half2 h[4]; } cv;
                cv.v = pr[lane + 32 * u];
#pragma unroll
                for (int o = 0; o < 4; ++o) {
                    float2 f = __half22float2(cv.h[o]);
                    fs[u * 8 + o * 2]     += f.x;
                    fs[u * 8 + o * 2 + 1] += f.y;
                }
            }
        }
        uint4* dst = (uint4*)&g_MX[(size_t)m * HID_];
#pragma unroll
        for (int u = 0; u < 3; ++u) {
            union { uint4 v; __half2 h[4]; } ov;
#pragma unroll
            for (int o = 0; o < 4; ++o)
                ov.h[o] = __floats2half2_rn(fs[u * 8 + o * 2] * inv, fs[u * 8 + o * 2 + 1] * inv);
            dst[lane + 32 * u] = ov.v;
        }
    }
    __syncthreads();

    const int r0 = tid >> 2;
    const int c0 = tid & 3;

    float pers[4][3];
#pragma unroll
    for (int i = 0; i < 4; ++i)
#pragma unroll
        for (int j = 0; j < 3; ++j) pers[i][j] = 0.0f;

    float acc[2][4][4];
#pragma unroll
    for (int mf = 0; mf < 2; ++mf)
#pragma unroll
        for (int nf = 0; nf < 4; ++nf)
#pragma unroll
            for (int q = 0; q < 4; ++q) acc[mf][nf][q] = 0.0f;

    // ---- prologue: pairs 0,1 (stages 0..3), one commit per pair ----
#pragma unroll
    for (int pp = 0; pp < 2; ++pp) {
#pragma unroll
        for (int q = 0; q < 2; ++q) {
            const int sg = pp * 2 + q;                   // stage 0..3, all in nt=0
            const int k0 = sg * 32;
            uint32_t sA = tile_base + pp * PAIR_BYTES + q * STAGE_BYTES;
            uint32_t sB = sA + 128 * ROW_PITCH;
#pragma unroll
            for (int it = 0; it < 2; ++it) {
                int r = r0 + it * 64;
                CPASYNC16(sA + r * ROW_PITCH + c0 * 16,
                          (const void*)&g_X[(size_t)(m0 + r) * KD_ + k0 + c0 * 8]);
            }
            CPASYNC16(sB + r0 * ROW_PITCH + c0 * 16,
                      (const void*)&g_W1t[(size_t)r0 * KD_ + k0 + c0 * 8]);
        }
        CPCOMMIT();
    }

    // ---- mainloop over 72 pairs ----
#pragma unroll 1
    for (int p = 0; p < IT_; ++p) {
        if (p < IT_ - 1) { CPWAIT1(); } else { CPWAIT0(); }
        __syncthreads();

        // prefetch pair p+2 into buffer (p+2)%3 (held pair p-1; all warps past its compute)
        if (p + 2 < IT_) {
            const int np = p + 2;
            uint32_t base = tile_base + (np % 3) * PAIR_BYTES;
#pragma unroll
            for (int q = 0; q < 2; ++q) {
                const int sg  = np * 2 + q;
                const int pk0 = (sg % KT_) * 32;
                const int pn0 = (sg / KT_) * 64;
                uint32_t sA = base + q * STAGE_BYTES;
                uint32_t sB = sA + 128 * ROW_PITCH;
#pragma unroll
                for (int it = 0; it < 2; ++it) {
                    int r = r0 + it * 64;
                    CPASYNC16(sA + r * ROW_PITCH + c0 * 16,
                              (const void*)&g_X[(size_t)(m0 + r) * KD_ + pk0 + c0 * 8]);
                }
                CPASYNC16(sB + r0 * ROW_PITCH + c0 * 16,
                          (const void*)&g_W1t[(size_t)(pn0 + r0) * KD_ + pk0 + c0 * 8]);
            }
            CPCOMMIT();
        }

        // ---- compute both stages of pair p ----
        {
            uint32_t pbase = tile_base + (p % 3) * PAIR_BYTES;
#pragma unroll
            for (int q = 0; q < 2; ++q) {
                uint32_t sA = pbase + q * STAGE_BYTES;
                uint32_t sB = sA + 128 * ROW_PITCH;
#pragma unroll
                for (int ks = 0; ks < 2; ++ks) {
                    uint32_t afr[2][4], bfr[2][4];
#pragma unroll
                    for (int mf = 0; mf < 2; ++mf) {
                        uint32_t addr = sA + (warpM * 32 + mf * 16 + (lane & 15)) * ROW_PITCH
                                           + (ks * 2 + (lane >> 4)) * 16;
                        ldsm4(afr[mf], addr);
                    }
#pragma unroll
                    for (int nq = 0; nq < 2; ++nq) {
                        uint32_t addr = sB + (warpN * 32 + nq * 16 + (lane & 7) + ((lane >> 4) & 1) * 8) * ROW_PITCH
                                           + (ks * 2 + ((lane >> 3) & 1)) * 16;
                        ldsm4(bfr[nq], addr);
                    }
#pragma unroll
                    for (int mf = 0; mf < 2; ++mf)
#pragma unroll
                        for (int nq = 0; nq < 2; ++nq) {
                            mma16816(acc[mf][nq * 2],     afr[mf], bfr[nq][0], bfr[nq][1]);
                            mma16816(acc[mf][nq * 2 + 1], afr[mf], bfr[nq][2], bfr[nq][3]);
                        }
                }
            }
        }

        // ---- n-tile boundary (every 6 pairs): fused epilogue ----
        if ((p % 6) == 5) {
            const int n0 = (p / 6) * 64;
#pragma unroll
            for (int mf = 0; mf < 2; ++mf) {
#pragma unroll
                for (int hr = 0; hr < 2; ++hr) {
                    const int rowL = warpM * 32 + mf * 16 + hr * 8 + (lane >> 2);
                    const size_t mrow = (size_t)(m0 + rowL) * HID_;
                    __half2 mh[4];
#pragma unroll
                    for (int nf = 0; nf < 4; ++nf)
                        mh[nf] = *(const __half2*)&g_MX[mrow + n0 + warpN * 32 + nf * 8 + (lane & 3) * 2];

                    float p12[12];
#pragma unroll
                    for (int o = 0; o < 12; ++o) p12[o] = 0.0f;
#pragma unroll
                    for (int nf = 0; nf < 4; ++nf) {
                        int col0 = n0 + warpN * 32 + nf * 8 + (lane & 3) * 2;
                        float2 mf2 = __half22float2(mh[nf]);
                        float v0 = fmaxf(acc[mf][nf][2 * hr]     + mf2.x + __ldg(&b1[col0]),     0.0f);
                        float v1 = fmaxf(acc[mf][nf][2 * hr + 1] + mf2.y + __ldg(&b1[col0 + 1]), 0.0f);
                        const float4* wp0 = (const float4*)(W2 + col0 * 12);
                        const float4* wp1 = (const float4*)(W2 + (col0 + 1) * 12);
                        float4 a0 = __ldg(wp0), a1 = __ldg(wp0 + 1), a2 = __ldg(wp0 + 2);
                        float4 d0 = __ldg(wp1), d1 = __ldg(wp1 + 1), d2 = __ldg(wp1 + 2);
                        p12[0]  += v0 * a0.x + v1 * d0.x;  p12[1]  += v0 * a0.y + v1 * d0.y;
                        p12[2]  += v0 * a0.z + v1 * d0.z;  p12[3]  += v0 * a0.w + v1 * d0.w;
                        p12[4]  += v0 * a1.x + v1 * d1.x;  p12[5]  += v0 * a1.y + v1 * d1.y;
                        p12[6]  += v0 * a1.z + v1 * d1.z;  p12[7]  += v0 * a1.w + v1 * d1.w;
                        p12[8]  += v0 * a2.x + v1 * d2.x;  p12[9]  += v0 * a2.y + v1 * d2.y;
                        p12[10] += v0 * a2.z + v1 * d2.z;  p12[11] += v0 * a2.w + v1 * d2.w;
                    }
#pragma unroll
                    for (int o = 0; o < 12; ++o) {
                        p12[o] += __shfl_xor_sync(0xffffffffu, p12[o], 1);
                        p12[o] += __shfl_xor_sync(0xffffffffu, p12[o], 2);
                    }
                    int q = lane & 3;
                    pers[mf * 2 + hr][0] += p12[3 * q + 0];
                    pers[mf * 2 + hr][1] += p12[3 * q + 1];
                    pers[mf * 2 + hr][2] += p12[3 * q + 2];
                }
            }
#pragma unroll
            for (int mf = 0; mf < 2; ++mf)
#pragma unroll
                for (int nf = 0; nf < 4; ++nf)
#pragma unroll
                    for (int q = 0; q < 4; ++q) acc[mf][nf][q] = 0.0f;
        }
    }

    // ---- cross-warpN reduce (reuse tile smem), then global write ----
    float* red = (float*)smem;
    __syncthreads();
    if (warpN == 1) {
#pragma unroll
        for (int i = 0; i < 4; ++i) {
            int mf = i >> 1, hr = i & 1;
            int rowL = warpM * 32 + mf * 16 + hr * 8 + (lane >> 2);
            int q = lane & 3;
#pragma unroll
            for (int j = 0; j < 3; ++j)
                red[rowL * 12 + 3 * q + j] = pers[i][j];
        }
    }
    __syncthreads();
    if (warpN == 0) {
#pragma unroll
        for (int i = 0; i < 4; ++i) {
            int mf = i >> 1, hr = i & 1;
            int rowL = warpM * 32 + mf * 16 + hr * 8 + (lane >> 2);
            int q = lane & 3;
            size_t row = (size_t)(m0 + rowL);
#pragma unroll
            for (int j = 0; j < 3; ++j) {
                int o = 3 * q + j;
                out[row * 12 + o] = pers[i][j] + red[rowL * 12 + o] + b2[o];
            }
        }
    }
}

// ---------------- launch ----------------
extern "C" void kernel_launch(void* const* d_in, const int* in_sizes, int n_in,
                              void* d_out, int out_size)
{
    const float* patch  = (const float*)d_in[0];
    const float* nodes  = (const float*)d_in[1];
    const int*   batch  = (const int*)d_in[2];
    const int*   mapper = (const int*)d_in[3];
    const float* W1     = (const float*)d_in[4];
    const float* b1     = (const float*)d_in[5];
    const float* W2     = (const float*)d_in[6];
    const float* b2     = (const float*)d_in[7];
    float*       out    = (float*)d_out;

    k_conv<<<(W1T_WORK + NX_WORK + PF_WORK + 255) / 256, 256>>>(W1, nodes, patch);  // 0
    dim3 pwgrid(BP_ / 64, HID_ / 128);
    k_pw<<<pwgrid, 256>>>();                                                        // 1
    cudaFuncSetAttribute(k_csr, cudaFuncAttributeMaxDynamicSharedMemorySize, N_ * 4);
    k_csr<<<1, 1024, N_ * 4>>>(mapper, batch);                                      // 2
    cudaFuncSetAttribute(k_gemm, cudaFuncAttributeMaxDynamicSharedMemorySize, SMEM_BYTES);
    k_gemm<<<M_ / 128, 256, SMEM_BYTES>>>(b1, W2, b2, out);                         // 3
}